// round 2
// baseline (speedup 1.0000x reference)
#include <cuda_runtime.h>

#define HWPX (1024*1024)
#define NB 8
#define NA 8
#define NK 16
#define NSEG 17
#define EPSV 1e-4f

// per-batch constant block layout (floats):
// [0,24)   : A copy, c-major: A[c*8+a]
// [24,48)  : pinv rows, [a][3]
// [48,56)  : mins (kept for debug)
// [56,64)  : dxinv
// [64,72)  : m2 = -mins*dxinv  (so u = fma(f, dxinv, m2))
// [72,416) : tab[a][k] as float2 (slope, intercept), 8*17*2 = 272 floats
#define CB_A    0
#define CB_PV   24
#define CB_MIN  48
#define CB_DXI  56
#define CB_M2   64
#define CB_TAB  72
#define CB_SIZE (72 + NA*NSEG*2)   // 344 floats

__device__ float g_consts[NB * CB_SIZE];

__global__ void precompute_kernel(const float* __restrict__ ys,
                                  const float* __restrict__ A) {
    int b = blockIdx.x;
    int t = threadIdx.x;
    const float* Ab = A + b * 3 * NA;
    float* cb = g_consts + b * CB_SIZE;

    if (t < 24) cb[CB_A + t] = Ab[t];

    if (t < NA) {
        int a = t;
        // full A in registers (broadcast loads)
        float Am[3][NA];
        #pragma unroll
        for (int c = 0; c < 3; c++)
            #pragma unroll
            for (int j = 0; j < NA; j++)
                Am[c][j] = Ab[c * NA + j];

        // M = A * A^T  (3x3, symmetric)
        float M[3][3];
        #pragma unroll
        for (int i = 0; i < 3; i++)
            #pragma unroll
            for (int j = 0; j < 3; j++) {
                float s = 0.f;
                #pragma unroll
                for (int k = 0; k < NA; k++) s += Am[i][k] * Am[j][k];
                M[i][j] = s;
            }

        // analytic 3x3 inverse
        float c00 = M[1][1]*M[2][2] - M[1][2]*M[2][1];
        float c01 = M[1][2]*M[2][0] - M[1][0]*M[2][2];
        float c02 = M[1][0]*M[2][1] - M[1][1]*M[2][0];
        float det = M[0][0]*c00 + M[0][1]*c01 + M[0][2]*c02;
        float id  = 1.0f / det;
        float inv[3][3];
        inv[0][0] = c00 * id;
        inv[1][0] = c01 * id;
        inv[2][0] = c02 * id;
        inv[0][1] = (M[0][2]*M[2][1] - M[0][1]*M[2][2]) * id;
        inv[1][1] = (M[0][0]*M[2][2] - M[0][2]*M[2][0]) * id;
        inv[2][1] = (M[0][1]*M[2][0] - M[0][0]*M[2][1]) * id;
        inv[0][2] = (M[0][1]*M[1][2] - M[0][2]*M[1][1]) * id;
        inv[1][2] = (M[0][2]*M[1][0] - M[0][0]*M[1][2]) * id;
        inv[2][2] = (M[0][0]*M[1][1] - M[0][1]*M[1][0]) * id;

        // pinv[a][c] = sum_k A[k][a] * inv[k][c]   (pinv = A^T (A A^T)^-1)
        #pragma unroll
        for (int c = 0; c < 3; c++) {
            float s = 0.f;
            #pragma unroll
            for (int k = 0; k < 3; k++) s += Am[k][a] * inv[k][c];
            cb[CB_PV + a * 3 + c] = s;
        }

        float mn = 0.f, mx = 0.f;
        #pragma unroll
        for (int c = 0; c < 3; c++) {
            float v = Am[c][a];
            mn += fminf(v, 0.f);
            mx += fmaxf(v, 0.f);
        }
        float dx  = (mx + EPSV - mn) / 17.0f;
        float dxi = 1.0f / dx;
        cb[CB_MIN + a] = mn;
        cb[CB_DXI + a] = dxi;
        cb[CB_M2  + a] = -mn * dxi;

        // ys_full = [mins, ys[0..15], maxs]
        float ysf[18];
        ysf[0]  = mn;
        ysf[17] = mx;
        #pragma unroll
        for (int k = 0; k < NK; k++)
            ysf[k + 1] = ys[(b * NA + a) * NK + k];

        // per-segment (slope, intercept): est = ys_hi - (xs_hi - f)*sl
        //                                     = (ys_hi - xs_hi*sl) + f*sl
        #pragma unroll
        for (int k = 0; k < NSEG; k++) {
            float sl    = (ysf[k + 1] - ysf[k]) / dx;
            float xs_hi = mn + (float)(k + 1) * dx;
            float c0    = ysf[k + 1] - xs_hi * sl;
            cb[CB_TAB + (a * NSEG + k) * 2 + 0] = sl;
            cb[CB_TAB + (a * NSEG + k) * 2 + 1] = c0;
        }
    }
}

__global__ __launch_bounds__(256)
void spline_main_kernel(const float* __restrict__ raw, float* __restrict__ out) {
    __shared__ float sc[CB_SIZE];
    const int b = blockIdx.y;
    {
        const float* cb = g_consts + b * CB_SIZE;
        for (int i = threadIdx.x; i < CB_SIZE; i += 256) sc[i] = cb[i];
    }
    __syncthreads();

    const float*  sA   = sc + CB_A;
    const float*  spv  = sc + CB_PV;
    const float*  sdxi = sc + CB_DXI;
    const float*  sm2  = sc + CB_M2;
    const float2* stab = (const float2*)(sc + CB_TAB);

    const size_t base = (size_t)b * 3 * HWPX;
    const int vidx = blockIdx.x * 256 + threadIdx.x;   // float4 index within plane

    float4 R  = ((const float4*)(raw + base          ))[vidx];
    float4 G  = ((const float4*)(raw + base +   HWPX ))[vidx];
    float4 Bv = ((const float4*)(raw + base + 2*HWPX ))[vidx];

    float rr[4] = {R.x,  R.y,  R.z,  R.w};
    float gg[4] = {G.x,  G.y,  G.z,  G.w};
    float bb[4] = {Bv.x, Bv.y, Bv.z, Bv.w};

    float a0[4], a1[4], a2[4];
    #pragma unroll
    for (int q = 0; q < 4; q++) { a0[q] = 0.f; a1[q] = 0.f; a2[q] = 0.f; }

    #pragma unroll
    for (int a = 0; a < NA; a++) {
        const float A0  = sA[a];
        const float A1  = sA[8 + a];
        const float A2  = sA[16 + a];
        const float dxi = sdxi[a];
        const float m2  = sm2[a];
        const float pv0 = spv[a * 3 + 0];
        const float pv1 = spv[a * 3 + 1];
        const float pv2 = spv[a * 3 + 2];
        #pragma unroll
        for (int q = 0; q < 4; q++) {
            float f = fmaf(rr[q], A0, fmaf(gg[q], A1, bb[q] * A2));
            float u = fmaf(f, dxi, m2);
            int   k = __float2int_rd(fminf(u, 16.0f));
            k = max(k, 0);
            float2 tc = stab[a * NSEG + k];
            float est = fmaf(f, tc.x, tc.y);
            a0[q] = fmaf(est, pv0, a0[q]);
            a1[q] = fmaf(est, pv1, a1[q]);
            a2[q] = fmaf(est, pv2, a2[q]);
        }
    }

    ((float4*)(out + base          ))[vidx] = make_float4(a0[0], a0[1], a0[2], a0[3]);
    ((float4*)(out + base +   HWPX ))[vidx] = make_float4(a1[0], a1[1], a1[2], a1[3]);
    ((float4*)(out + base + 2*HWPX ))[vidx] = make_float4(a2[0], a2[1], a2[2], a2[3]);
}

extern "C" void kernel_launch(void* const* d_in, const int* in_sizes, int n_in,
                              void* d_out, int out_size) {
    const float* raw = (const float*)d_in[0];
    const float* ys  = (const float*)d_in[1];
    const float* A   = (const float*)d_in[2];
    float* out = (float*)d_out;

    precompute_kernel<<<NB, 32>>>(ys, A);

    dim3 grid(HWPX / (256 * 4), NB);
    spline_main_kernel<<<grid, 256>>>(raw, out);
}